// round 1
// baseline (speedup 1.0000x reference)
#include <cuda_runtime.h>
#include <math.h>

#define S_LEN 8192
#define H_DIM 1024
#define N_OUT 3072
#define NHEAD 8
#define HDIM  128

// Scratch (allocation-free per the rules): Q/K/V in [head][s][d] layout.
__device__ float g_Q[NHEAD * S_LEN * HDIM];
__device__ float g_K[NHEAD * S_LEN * HDIM];
__device__ float g_V[NHEAD * S_LEN * HDIM];

// ---------------------------------------------------------------------------
// Kernel A: QKV = X @ W^T + bias, scattered into g_Q/g_K/g_V ([head][s][d]).
// X: [8192][1024] row-major, W: [3072][1024] row-major (both K-contiguous).
// 64x64 block tile, K-step 32, 256 threads, 4x4 micro-tile.
// ---------------------------------------------------------------------------
__global__ __launch_bounds__(256) void qkv_gemm_kernel(
    const float* __restrict__ X, const float* __restrict__ W,
    const float* __restrict__ bias)
{
    __shared__ __align__(16) float sA[32][68];  // sA[k][m] (transposed)
    __shared__ __align__(16) float sB[32][68];  // sB[k][n]

    const int m0 = blockIdx.y * 64;
    const int n0 = blockIdx.x * 64;
    const int tid = threadIdx.x;
    const int tx = tid & 15, ty = tid >> 4;

    float acc[4][4] = {};

    for (int k0 = 0; k0 < H_DIM; k0 += 32) {
        // Load 64x32 tiles of A and B (512 float4 each; 2 per thread per operand)
        #pragma unroll
        for (int r = 0; r < 2; r++) {
            int f = tid + r * 256;
            int row = f >> 3, c4 = f & 7;
            float4 a = *(const float4*)(X + (size_t)(m0 + row) * H_DIM + k0 + c4 * 4);
            sA[c4*4+0][row] = a.x; sA[c4*4+1][row] = a.y;
            sA[c4*4+2][row] = a.z; sA[c4*4+3][row] = a.w;
            float4 b = *(const float4*)(W + (size_t)(n0 + row) * H_DIM + k0 + c4 * 4);
            sB[c4*4+0][row] = b.x; sB[c4*4+1][row] = b.y;
            sB[c4*4+2][row] = b.z; sB[c4*4+3][row] = b.w;
        }
        __syncthreads();
        #pragma unroll 8
        for (int kk = 0; kk < 32; kk++) {
            float4 av = *(const float4*)(&sA[kk][ty * 4]);
            float4 bv = *(const float4*)(&sB[kk][tx * 4]);
            float a[4] = {av.x, av.y, av.z, av.w};
            float b[4] = {bv.x, bv.y, bv.z, bv.w};
            #pragma unroll
            for (int i = 0; i < 4; i++)
                #pragma unroll
                for (int j = 0; j < 4; j++)
                    acc[i][j] = fmaf(a[i], b[j], acc[i][j]);
        }
        __syncthreads();
    }

    // Epilogue: bias + scatter to [head][s][d]. 4 consecutive n stay inside
    // one (type, head) since tiles are 64-aligned and head_dim = 128.
    const int n_base = n0 + tx * 4;
    const int type = n_base >> 10;           // 0:Q 1:K 2:V
    const int head = (n_base & 1023) >> 7;
    const int d = n_base & 127;
    float* dst = (type == 0) ? g_Q : (type == 1) ? g_K : g_V;
    float4 bs = *(const float4*)(bias + n_base);
    #pragma unroll
    for (int i = 0; i < 4; i++) {
        int m = m0 + ty * 4 + i;
        float4 o;
        o.x = acc[i][0] + bs.x; o.y = acc[i][1] + bs.y;
        o.z = acc[i][2] + bs.z; o.w = acc[i][3] + bs.w;
        *(float4*)(dst + ((size_t)head * S_LEN + m) * HDIM + d) = o;
    }
}

// ---------------------------------------------------------------------------
// Kernel B: RoPE on Q and K (in place); softmax scale folded into Q.
// grid = S_LEN blocks, 512 threads: head = tid>>6, d = tid&63 (pair d, d+64)
// ---------------------------------------------------------------------------
__global__ __launch_bounds__(512) void rope_kernel(
    const float* __restrict__ cosp, const float* __restrict__ sinp)
{
    const int s = blockIdx.x;
    const int tid = threadIdx.x;
    const int head = tid >> 6;
    const int d = tid & 63;
    const float SCALE = 0.08838834764831845f;  // 128^-0.5

    float c1 = cosp[s * HDIM + d],      s1 = sinp[s * HDIM + d];
    float c2 = cosp[s * HDIM + d + 64], s2 = sinp[s * HDIM + d + 64];

    size_t base = ((size_t)head * S_LEN + s) * HDIM;

    float q1 = g_Q[base + d], q2 = g_Q[base + d + 64];
    g_Q[base + d]      = (q1 * c1 - q2 * s1) * SCALE;
    g_Q[base + d + 64] = (q2 * c2 + q1 * s2) * SCALE;

    float k1 = g_K[base + d], k2 = g_K[base + d + 64];
    g_K[base + d]      = k1 * c1 - k2 * s1;
    g_K[base + d + 64] = k2 * c2 + k1 * s2;
}

// ---------------------------------------------------------------------------
// Kernel C: causal flash attention, fp32.
// grid = (128 q-blocks [reversed for load balance], 8 heads), 256 threads.
// BLOCK_M = BLOCK_N = 64. Q/K staged transposed ([d][row]) for conflict-free
// float4 LDS; P staged via smem for the PV matmul. Online softmax.
// smem = 120832 B (dynamic).
// ---------------------------------------------------------------------------
__global__ __launch_bounds__(256) void attn_kernel(float* __restrict__ out)
{
    extern __shared__ float sm[];
    float* sQ = sm;               // [128][68]  sQ[k][m]
    float* sK = sQ + 128 * 68;    // [128][68]  sK[k][n]
    float* sV = sK + 128 * 68;    // [64][132]  sV[n][d]
    float* sP = sV + 64 * 132;    // [64][68]   sP[n][m]

    const int head = blockIdx.y;
    const int mb = (int)gridDim.x - 1 - (int)blockIdx.x;  // heavy blocks first
    const int q0 = mb * 64;
    const int tid = threadIdx.x;
    const int tx = tid & 15, ty = tid >> 4;

    const float* Qh = g_Q + (size_t)head * S_LEN * HDIM;
    const float* Kh = g_K + (size_t)head * S_LEN * HDIM;
    const float* Vh = g_V + (size_t)head * S_LEN * HDIM;

    // Load Q tile transposed (once per CTA)
    for (int f = tid; f < 2048; f += 256) {
        int row = f >> 5, c4 = f & 31;
        float4 v = *(const float4*)(Qh + (size_t)(q0 + row) * HDIM + c4 * 4);
        sQ[(c4*4+0)*68 + row] = v.x;
        sQ[(c4*4+1)*68 + row] = v.y;
        sQ[(c4*4+2)*68 + row] = v.z;
        sQ[(c4*4+3)*68 + row] = v.w;
    }

    float m_i[4], l_i[4], acc[4][8];
    #pragma unroll
    for (int i = 0; i < 4; i++) {
        m_i[i] = -INFINITY; l_i[i] = 0.f;
        #pragma unroll
        for (int j = 0; j < 8; j++) acc[i][j] = 0.f;
    }

    for (int nb = 0; nb <= mb; nb++) {
        const int k0 = nb * 64;

        // Load K (transposed) and V (natural) tiles
        for (int f = tid; f < 2048; f += 256) {
            int row = f >> 5, c4 = f & 31;
            float4 v = *(const float4*)(Kh + (size_t)(k0 + row) * HDIM + c4 * 4);
            sK[(c4*4+0)*68 + row] = v.x;
            sK[(c4*4+1)*68 + row] = v.y;
            sK[(c4*4+2)*68 + row] = v.z;
            sK[(c4*4+3)*68 + row] = v.w;
            float4 w = *(const float4*)(Vh + (size_t)(k0 + row) * HDIM + c4 * 4);
            *(float4*)(sV + row * 132 + c4 * 4) = w;
        }
        __syncthreads();

        // S = Q K^T  (scale already folded into Q)
        float sv[4][4] = {};
        #pragma unroll 8
        for (int k = 0; k < 128; k++) {
            float4 qv = *(const float4*)(sQ + k * 68 + ty * 4);
            float4 kv = *(const float4*)(sK + k * 68 + tx * 4);
            float a[4] = {qv.x, qv.y, qv.z, qv.w};
            float b[4] = {kv.x, kv.y, kv.z, kv.w};
            #pragma unroll
            for (int i = 0; i < 4; i++)
                #pragma unroll
                for (int j = 0; j < 4; j++)
                    sv[i][j] = fmaf(a[i], b[j], sv[i][j]);
        }

        // Causal mask on the diagonal block only
        if (nb == mb) {
            #pragma unroll
            for (int i = 0; i < 4; i++)
                #pragma unroll
                for (int j = 0; j < 4; j++)
                    if (k0 + tx * 4 + j > q0 + ty * 4 + i) sv[i][j] = -1e30f;
        }

        // Online softmax update (row stats shared by the 16 tx threads)
        float alpha[4];
        #pragma unroll
        for (int i = 0; i < 4; i++) {
            float mx = fmaxf(fmaxf(sv[i][0], sv[i][1]), fmaxf(sv[i][2], sv[i][3]));
            #pragma unroll
            for (int off = 8; off > 0; off >>= 1)
                mx = fmaxf(mx, __shfl_xor_sync(0xffffffffu, mx, off));
            float m_new = fmaxf(m_i[i], mx);
            alpha[i] = __expf(m_i[i] - m_new);   // exp(-inf)=0 on first block
            m_i[i] = m_new;

            float rs = 0.f;
            #pragma unroll
            for (int j = 0; j < 4; j++) {
                float p = __expf(sv[i][j] - m_new);
                sv[i][j] = p;
                rs += p;
            }
            #pragma unroll
            for (int off = 8; off > 0; off >>= 1)
                rs += __shfl_xor_sync(0xffffffffu, rs, off);
            l_i[i] = l_i[i] * alpha[i] + rs;
            #pragma unroll
            for (int j = 0; j < 8; j++) acc[i][j] *= alpha[i];
        }

        // Stage P transposed for the PV matmul
        #pragma unroll
        for (int i = 0; i < 4; i++)
            #pragma unroll
            for (int j = 0; j < 4; j++)
                sP[(tx * 4 + j) * 68 + ty * 4 + i] = sv[i][j];
        __syncthreads();

        // O += P @ V
        #pragma unroll 2
        for (int n = 0; n < 64; n++) {
            float4 pv = *(const float4*)(sP + n * 68 + ty * 4);
            float4 v0 = *(const float4*)(sV + n * 132 + tx * 8);
            float4 v1 = *(const float4*)(sV + n * 132 + tx * 8 + 4);
            float p[4] = {pv.x, pv.y, pv.z, pv.w};
            float vr[8] = {v0.x, v0.y, v0.z, v0.w, v1.x, v1.y, v1.z, v1.w};
            #pragma unroll
            for (int i = 0; i < 4; i++)
                #pragma unroll
                for (int j = 0; j < 8; j++)
                    acc[i][j] = fmaf(p[i], vr[j], acc[i][j]);
        }
        __syncthreads();
    }

    // Epilogue: normalize and write out[s][head][d] (row stride 1024)
    #pragma unroll
    for (int i = 0; i < 4; i++) {
        float inv = 1.0f / l_i[i];
        size_t base = (size_t)(q0 + ty * 4 + i) * (NHEAD * HDIM) + head * HDIM + tx * 8;
        float4 o0, o1;
        o0.x = acc[i][0] * inv; o0.y = acc[i][1] * inv;
        o0.z = acc[i][2] * inv; o0.w = acc[i][3] * inv;
        o1.x = acc[i][4] * inv; o1.y = acc[i][5] * inv;
        o1.z = acc[i][6] * inv; o1.w = acc[i][7] * inv;
        *(float4*)(out + base) = o0;
        *(float4*)(out + base + 4) = o1;
    }
}

// ---------------------------------------------------------------------------
extern "C" void kernel_launch(void* const* d_in, const int* in_sizes, int n_in,
                              void* d_out, int out_size)
{
    const float* x  = (const float*)d_in[0];  // layernorm_output [8192][1][1024]
    const float* fc = (const float*)d_in[1];  // freqs_cos [8192][1][1][128]
    const float* fs = (const float*)d_in[2];  // freqs_sin
    const float* w  = (const float*)d_in[3];  // qkv_weight [3072][1024]
    const float* b  = (const float*)d_in[4];  // qkv_bias [3072]
    float* out = (float*)d_out;               // [1][8192][8][128] fp32

    qkv_gemm_kernel<<<dim3(N_OUT / 64, S_LEN / 64), 256>>>(x, w, b);
    rope_kernel<<<S_LEN, 512>>>(fc, fs);

    const size_t attn_smem = (size_t)(2 * 128 * 68 + 64 * 132 + 64 * 68) * sizeof(float);
    cudaFuncSetAttribute(attn_kernel, cudaFuncAttributeMaxDynamicSharedMemorySize,
                         (int)attn_smem);
    attn_kernel<<<dim3(S_LEN / 64, NHEAD), 256, attn_smem>>>(out);
}